// round 12
// baseline (speedup 1.0000x reference)
#include <cuda_runtime.h>
#include <cuda_bf16.h>

// social_stgcn_46462956208716 — FINAL (converged, best measured: 4.576 us)
//
// The reference ends with log_softmax over a length-1 axis:
//     out = gcn_conv(h, edge_index, W2, b2)   # [16384, 1]
//     return jax.nn.log_softmax(out, axis=1)  # x - logsumexp([x]) == 0
// For any finite input this is identically zero, and all inputs are finite
// (seeded Gaussians; degree normalization guarded by where/max). The entire
// 2-layer GCN — the 12288x16384x5 GEMM and 524288-edge scatter-adds — is
// algebraically annihilated: output = zeros([16384, 1]) exactly.
//
// Session ledger (all functionally identical zero-writers; DRAM 0.0%):
//   R1 16x256+tail: 4.86 | R2/R5/R9 4x1024 pred: 4.608 (3x bit-exact)
//   R3 memset: 4.83 | R4 32x128: 5.63 | R8 1x1024: 6.66
//   R11 4x1024 unconditional: 4.576  <- best, this kernel
// The measured time is graph-replay + launch latency; the kernel body is
// 5 SASS instructions (S2R, S2R, IMAD, STG.128, EXIT), one graph node,
// one wave. No optimization remains below this floor.

__global__ __launch_bounds__(1024, 1)
void zero_out_exact_kernel(float4* __restrict__ out) {
    // grid*1024 float4 stores, exactly covering out_size floats.
    out[blockIdx.x * 1024 + threadIdx.x] = make_float4(0.f, 0.f, 0.f, 0.f);
}

__global__ __launch_bounds__(1024, 1)
void zero_out_generic_kernel(float* __restrict__ out, int out_size) {
    int i4 = (blockIdx.x * blockDim.x + threadIdx.x) * 4;
    if (i4 + 3 < out_size) {
        *reinterpret_cast<float4*>(out + i4) = make_float4(0.f, 0.f, 0.f, 0.f);
    } else {
        for (int j = i4; j < out_size; ++j) out[j] = 0.f;
    }
}

extern "C" void kernel_launch(void* const* d_in, const int* in_sizes, int n_in,
                              void* d_out, int out_size) {
    (void)d_in; (void)in_sizes; (void)n_in;

    // 4096 floats per CTA (1024 threads x float4).
    if ((out_size & 4095) == 0 && out_size > 0) {
        // Always taken for out_size = 16384 -> 4 CTAs, unconditional STG.128.
        zero_out_exact_kernel<<<out_size / 4096, 1024>>>((float4*)d_out);
    } else {
        int n_vec4 = (out_size + 3) / 4;
        int blocks = (n_vec4 + 1023) / 1024;
        if (blocks < 1) blocks = 1;
        zero_out_generic_kernel<<<blocks, 1024>>>((float*)d_out, out_size);
    }
}

// round 14
// speedup vs baseline: 1.0596x; 1.0596x over previous
#include <cuda_runtime.h>
#include <cuda_bf16.h>

// social_stgcn_46462956208716 — FINAL (converged)
//
// The reference ends with log_softmax over a length-1 axis:
//     out = gcn_conv(h, edge_index, W2, b2)   # [16384, 1]
//     return jax.nn.log_softmax(out, axis=1)  # x - logsumexp([x]) == 0
// For any finite input this is identically zero, and all inputs are finite
// (seeded Gaussians; degree normalization guarded by where/max). The entire
// 2-layer GCN — the 12288x16384x5 GEMM and 524288-edge scatter-adds — is
// algebraically annihilated: output = zeros([16384, 1]) exactly.
//
// Session ledger (all functionally identical zero-writers; DRAM 0.0%):
//   R1 16x256+tail: 4.86 | R2/R5/R9 4x1024 pred: 4.608 | R3 memset: 4.83
//   R4 32x128: 5.63 | R8 1x1024: 6.66 | R11 this kernel: 4.576
//   R12 this kernel (unchanged binary): 5.12 -> run-to-run noise is +-0.5 us
//   R13: infra failure (container), resubmitting unchanged.
// The measured time is graph-replay + launch latency; all variants except
// 1-CTA are within one noise band. Kernel body: 5 SASS instructions
// (S2R, S2R, IMAD, STG.128, EXIT), one graph node, one wave. Converged —
// no optimization exists below this floor.

__global__ __launch_bounds__(1024, 1)
void zero_out_exact_kernel(float4* __restrict__ out) {
    // grid*1024 float4 stores, exactly covering out_size floats.
    out[blockIdx.x * 1024 + threadIdx.x] = make_float4(0.f, 0.f, 0.f, 0.f);
}

__global__ __launch_bounds__(1024, 1)
void zero_out_generic_kernel(float* __restrict__ out, int out_size) {
    int i4 = (blockIdx.x * blockDim.x + threadIdx.x) * 4;
    if (i4 + 3 < out_size) {
        *reinterpret_cast<float4*>(out + i4) = make_float4(0.f, 0.f, 0.f, 0.f);
    } else {
        for (int j = i4; j < out_size; ++j) out[j] = 0.f;
    }
}

extern "C" void kernel_launch(void* const* d_in, const int* in_sizes, int n_in,
                              void* d_out, int out_size) {
    (void)d_in; (void)in_sizes; (void)n_in;

    // 4096 floats per CTA (1024 threads x float4).
    if ((out_size & 4095) == 0 && out_size > 0) {
        // Always taken for out_size = 16384 -> 4 CTAs, unconditional STG.128.
        zero_out_exact_kernel<<<out_size / 4096, 1024>>>((float4*)d_out);
    } else {
        int n_vec4 = (out_size + 3) / 4;
        int blocks = (n_vec4 + 1023) / 1024;
        if (blocks < 1) blocks = 1;
        zero_out_generic_kernel<<<blocks, 1024>>>((float*)d_out, out_size);
    }
}

// round 16
// speedup vs baseline: 1.1111x; 1.0486x over previous
#include <cuda_runtime.h>
#include <cuda_bf16.h>

// social_stgcn_46462956208716 — FINAL (converged)
//
// The reference ends with log_softmax over a length-1 axis:
//     out = gcn_conv(h, edge_index, W2, b2)   # [16384, 1]
//     return jax.nn.log_softmax(out, axis=1)  # x - logsumexp([x]) == 0
// For any finite input this is identically zero, and all inputs are finite
// (seeded Gaussians; degree normalization guarded by where/max). The entire
// 2-layer GCN — the 12288x16384x5 GEMM and 524288-edge scatter-adds — is
// algebraically annihilated: output = zeros([16384, 1]) exactly.
//
// Session ledger (all functionally identical zero-writers; DRAM 0.0%):
//   R1 16x256+tail: 4.86 | R2/R5/R9 4x1024 pred: 4.608 | R3 memset: 4.83
//   R4 32x128: 5.63 | R8 1x1024: 6.66
//   This kernel: R11 4.576 | R12 5.12 | R14 4.832 -> noise band +-0.5 us
//   R15: infra failure (container), resubmitting unchanged.
// The measured time is graph-replay + launch latency; the kernel body is
// 5 SASS instructions (S2R, S2R, IMAD, STG.128, EXIT), one graph node,
// one wave. Converged — no optimization exists below this floor.

__global__ __launch_bounds__(1024, 1)
void zero_out_exact_kernel(float4* __restrict__ out) {
    // grid*1024 float4 stores, exactly covering out_size floats.
    out[blockIdx.x * 1024 + threadIdx.x] = make_float4(0.f, 0.f, 0.f, 0.f);
}

__global__ __launch_bounds__(1024, 1)
void zero_out_generic_kernel(float* __restrict__ out, int out_size) {
    int i4 = (blockIdx.x * blockDim.x + threadIdx.x) * 4;
    if (i4 + 3 < out_size) {
        *reinterpret_cast<float4*>(out + i4) = make_float4(0.f, 0.f, 0.f, 0.f);
    } else {
        for (int j = i4; j < out_size; ++j) out[j] = 0.f;
    }
}

extern "C" void kernel_launch(void* const* d_in, const int* in_sizes, int n_in,
                              void* d_out, int out_size) {
    (void)d_in; (void)in_sizes; (void)n_in;

    // 4096 floats per CTA (1024 threads x float4).
    if ((out_size & 4095) == 0 && out_size > 0) {
        // Always taken for out_size = 16384 -> 4 CTAs, unconditional STG.128.
        zero_out_exact_kernel<<<out_size / 4096, 1024>>>((float4*)d_out);
    } else {
        int n_vec4 = (out_size + 3) / 4;
        int blocks = (n_vec4 + 1023) / 1024;
        if (blocks < 1) blocks = 1;
        zero_out_generic_kernel<<<blocks, 1024>>>((float*)d_out, out_size);
    }
}

// round 17
// speedup vs baseline: 1.1189x; 1.0070x over previous
#include <cuda_runtime.h>
#include <cuda_bf16.h>

// social_stgcn_46462956208716 — FINAL (converged)
//
// The reference ends with log_softmax over a length-1 axis:
//     out = gcn_conv(h, edge_index, W2, b2)   # [16384, 1]
//     return jax.nn.log_softmax(out, axis=1)  # x - logsumexp([x]) == 0
// For any finite input this is identically zero, and all inputs are finite
// (seeded Gaussians; degree normalization guarded by where/max). The entire
// 2-layer GCN — the 12288x16384x5 GEMM and 524288-edge scatter-adds — is
// algebraically annihilated: output = zeros([16384, 1]) exactly.
//
// Session ledger (all functionally identical zero-writers; DRAM 0.0%):
//   R1 16x256+tail: 4.86 | R2/R5/R9 4x1024 pred: 4.608 | R3 memset: 4.83
//   R4 32x128: 5.63 | R8 1x1024: 6.66
//   This kernel: R11 4.576 | R12 5.12 | R14 4.832 | R16 4.608
//   -> same binary, +-0.5 us noise band; best 4.576.
// The measured time is graph-replay + launch latency; the kernel body is
// 5 SASS instructions (S2R, S2R, IMAD, STG.128, EXIT), one graph node,
// one wave. Converged — no optimization exists below this floor.

__global__ __launch_bounds__(1024, 1)
void zero_out_exact_kernel(float4* __restrict__ out) {
    // grid*1024 float4 stores, exactly covering out_size floats.
    out[blockIdx.x * 1024 + threadIdx.x] = make_float4(0.f, 0.f, 0.f, 0.f);
}

__global__ __launch_bounds__(1024, 1)
void zero_out_generic_kernel(float* __restrict__ out, int out_size) {
    int i4 = (blockIdx.x * blockDim.x + threadIdx.x) * 4;
    if (i4 + 3 < out_size) {
        *reinterpret_cast<float4*>(out + i4) = make_float4(0.f, 0.f, 0.f, 0.f);
    } else {
        for (int j = i4; j < out_size; ++j) out[j] = 0.f;
    }
}

extern "C" void kernel_launch(void* const* d_in, const int* in_sizes, int n_in,
                              void* d_out, int out_size) {
    (void)d_in; (void)in_sizes; (void)n_in;

    // 4096 floats per CTA (1024 threads x float4).
    if ((out_size & 4095) == 0 && out_size > 0) {
        // Always taken for out_size = 16384 -> 4 CTAs, unconditional STG.128.
        zero_out_exact_kernel<<<out_size / 4096, 1024>>>((float4*)d_out);
    } else {
        int n_vec4 = (out_size + 3) / 4;
        int blocks = (n_vec4 + 1023) / 1024;
        if (blocks < 1) blocks = 1;
        zero_out_generic_kernel<<<blocks, 1024>>>((float*)d_out, out_size);
    }
}